// round 11
// baseline (speedup 1.0000x reference)
#include <cuda_runtime.h>
#include <cuda_fp16.h>
#include <math.h>
#include <stdint.h>

// Problem constants
#define BB   64
#define HH   28
#define WW   28
#define CC   384
#define TT   784      // HH*WW
#define HK   13       // (28-3)/2+1
#define TK   169      // 13*13
#define NHEAD 6
#define DD   64
#define EPSV 1e-3f
#define CW   (CC/2)   // 192 half2-words per row

// Scratch (device globals). Activations fp16; weights k-paired [n][k/2].
__device__ __half  g_qc[(size_t)BB*TT*CC];
__device__ __half  g_kc[(size_t)BB*TK*CC];
__device__ __half  g_vc[(size_t)BB*TK*CC];
__device__ __half  g_Q [(size_t)BB*TT*CC];
__device__ __half  g_K [(size_t)BB*TK*CC];
__device__ __half  g_V [(size_t)BB*TK*CC];
__device__ __half  g_O [(size_t)BB*TT*CC];
__device__ uint32_t g_Wqt[(size_t)CC*CW];
__device__ uint32_t g_Wkt[(size_t)CC*CW];
__device__ uint32_t g_Wvt[(size_t)CC*CW];
__device__ uint32_t g_Wot[(size_t)CC*CW];

// ---------------------------------------------------------------------------
// helpers
// ---------------------------------------------------------------------------
__device__ __forceinline__ uint32_t packh2(float a, float b) {
    __half2 h = __floats2half2_rn(a, b);
    return *reinterpret_cast<uint32_t*>(&h);
}

__device__ __forceinline__ void mma16(float* c, const uint32_t* a, const uint32_t* b) {
    asm volatile(
        "mma.sync.aligned.m16n8k16.row.col.f32.f16.f16.f32 "
        "{%0,%1,%2,%3}, {%4,%5,%6,%7}, {%8,%9}, {%0,%1,%2,%3};"
        : "+f"(c[0]), "+f"(c[1]), "+f"(c[2]), "+f"(c[3])
        : "r"(a[0]), "r"(a[1]), "r"(a[2]), "r"(a[3]), "r"(b[0]), "r"(b[1]));
}

__device__ __forceinline__ void ldsm_x4(uint32_t* r, uint32_t addr) {
    asm volatile("ldmatrix.sync.aligned.m8n8.x4.shared.b16 {%0,%1,%2,%3}, [%4];"
                 : "=r"(r[0]), "=r"(r[1]), "=r"(r[2]), "=r"(r[3]) : "r"(addr));
}
__device__ __forceinline__ void ldsm_x4t(uint32_t* r, uint32_t addr) {
    asm volatile("ldmatrix.sync.aligned.m8n8.x4.trans.shared.b16 {%0,%1,%2,%3}, [%4];"
                 : "=r"(r[0]), "=r"(r[1]), "=r"(r[2]), "=r"(r[3]) : "r"(addr));
}

__device__ __forceinline__ void cp16(uint32_t dst_smem, const void* src, bool pred) {
    int sz = pred ? 16 : 0;   // sz=0 -> 16B zero-fill
    asm volatile("cp.async.ca.shared.global [%0], [%1], 16, %2;"
                 :: "r"(dst_smem), "l"(src), "r"(sz));
}
__device__ __forceinline__ void cp_commit() { asm volatile("cp.async.commit_group;"); }

// ---------------------------------------------------------------------------
// Weight conversion: fp32 [k][n] -> fp16 k-paired [n][k/2] words. One-shot.
// ---------------------------------------------------------------------------
__global__ void cvt_weights(const float* __restrict__ Wq, const float* __restrict__ Wk,
                            const float* __restrict__ Wv, const float* __restrict__ Wo)
{
    __shared__ float tile[32][33];
    const float* W = (blockIdx.z == 0) ? Wq : (blockIdx.z == 1) ? Wk
                   : (blockIdx.z == 2) ? Wv : Wo;
    uint32_t* out = (blockIdx.z == 0) ? g_Wqt : (blockIdx.z == 1) ? g_Wkt
                  : (blockIdx.z == 2) ? g_Wvt : g_Wot;
    int k0 = blockIdx.x * 32, n0 = blockIdx.y * 32;
    int tx = threadIdx.x, ty = threadIdx.y;
    tile[ty][tx] = W[(size_t)(k0 + ty)*CC + n0 + tx];
    __syncthreads();
    if (tx < 16)
        out[(size_t)(n0 + ty)*CW + (k0 >> 1) + tx] =
            packh2(tile[2*tx][ty], tile[2*tx + 1][ty]);
}

// ---------------------------------------------------------------------------
// Fused depthwise 3x3 conv + BN (q stride1 SAME; k,v stride2 VALID on odd rows)
// ---------------------------------------------------------------------------
__global__ __launch_bounds__(CC)
void dwbn_fused(const float* __restrict__ x,
                const float* __restrict__ wq, const float* __restrict__ qg,
                const float* __restrict__ qb, const float* __restrict__ qm,
                const float* __restrict__ qv,
                const float* __restrict__ wk, const float* __restrict__ kg,
                const float* __restrict__ kb, const float* __restrict__ km,
                const float* __restrict__ kvv,
                const float* __restrict__ wv, const float* __restrict__ vg,
                const float* __restrict__ vb, const float* __restrict__ vm,
                const float* __restrict__ vvv,
                __half* __restrict__ outq, __half* __restrict__ outk,
                __half* __restrict__ outv)
{
    int c = threadIdx.x;
    int by = blockIdx.x;
    int b  = by / HH;
    int y  = by - b * HH;
    bool kvrow = (y & 1) && (y <= 2*(HK-1) + 1);
    int yk = y >> 1;

    float Wq9[9], Wk9[9], Wv9[9];
#pragma unroll
    for (int i = 0; i < 9; ++i) Wq9[i] = wq[i*CC + c];
    float scq = qg[c] * rsqrtf(qv[c] + EPSV);
    float shq = qb[c] - scq * qm[c];
    float sck = 0.f, shk = 0.f, scv = 0.f, shv = 0.f;
    if (kvrow) {
#pragma unroll
        for (int i = 0; i < 9; ++i) { Wk9[i] = wk[i*CC + c]; Wv9[i] = wv[i*CC + c]; }
        sck = kg[c] * rsqrtf(kvv[c] + EPSV);
        shk = kb[c] - sck * km[c];
        scv = vg[c] * rsqrtf(vvv[c] + EPSV);
        shv = vb[c] - scv * vm[c];
    }

    const float* xr0 = x + ((size_t)b*TT + (y-1)*WW)*CC + c;
    const float* xr1 = x + ((size_t)b*TT + (y  )*WW)*CC + c;
    const float* xr2 = x + ((size_t)b*TT + (y+1)*WW)*CC + c;
    bool ok0 = (y > 0), ok2 = (y < HH-1);

    __half* oq  = outq + ((size_t)b*TT + y*WW)*CC + c;
    __half* ok_ = outk + ((size_t)b*TK + yk*HK)*CC + c;
    __half* ov_ = outv + ((size_t)b*TK + yk*HK)*CC + c;

    float win[3][3];
#pragma unroll
    for (int dx = 0; dx < 3; ++dx)
#pragma unroll
        for (int dy = 0; dy < 3; ++dy) win[dx][dy] = 0.f;

    for (int col = 0; col <= WW; ++col) {
        if (col < WW) {
            size_t off = (size_t)col * CC;
            win[2][0] = ok0 ? xr0[off] : 0.f;
            win[2][1] = xr1[off];
            win[2][2] = ok2 ? xr2[off] : 0.f;
        } else {
            win[2][0] = win[2][1] = win[2][2] = 0.f;
        }

        if (col >= 1) {
            int j = col - 1;
            float acc = 0.f;
#pragma unroll
            for (int dy = 0; dy < 3; ++dy)
#pragma unroll
                for (int dx = 0; dx < 3; ++dx)
                    acc += win[dx][dy] * Wq9[dy*3 + dx];
            oq[(size_t)j*CC] = __float2half_rn(scq * acc + shq);

            if (kvrow && col >= 2 && !(col & 1) && col <= 2*(HK-1) + 2) {
                int xk = (col - 2) >> 1;
                float ak = 0.f, av = 0.f;
#pragma unroll
                for (int dy = 0; dy < 3; ++dy)
#pragma unroll
                    for (int dx = 0; dx < 3; ++dx) {
                        float xv = win[dx][dy];
                        ak += xv * Wk9[dy*3 + dx];
                        av += xv * Wv9[dy*3 + dx];
                    }
                ok_[(size_t)xk*CC] = __float2half_rn(sck * ak + shk);
                ov_[(size_t)xk*CC] = __float2half_rn(scv * av + shv);
            }
        }
#pragma unroll
        for (int dy = 0; dy < 3; ++dy) {
            win[0][dy] = win[1][dy];
            win[1][dy] = win[2][dy];
        }
    }
}

// ---------------------------------------------------------------------------
// FP16 GEMM body: BK=64 halves, 3-stage cp.async, ONE syncthreads per K-iter
// (6 iters). 256 threads (8 warps 2m x 4n), block 128x128, warp 64x32.
// Stage = A(128x36w) + B(128x36w) = 36864B; 3 stages = 110592B dyn smem.
// ---------------------------------------------------------------------------
#define AST 36
#define BST 36
#define NT  6            // 384/64
#define STG 3
#define STAGE_B 36864u
#define BOFF  18432u

__device__ __forceinline__ void gemm_body(
    const __half* __restrict__ A, const uint32_t* __restrict__ W2,
    const float* __restrict__ bias, __half* __restrict__ Ch,
    float* __restrict__ Cf, int M, int bm, int bn, uint32_t smem_u, int tid)
{
    int warp = tid >> 5;
    int lane = tid & 31;
    int g    = lane >> 2;
    int tg   = lane & 3;
    int wm   = (warp >> 2) * 64;
    int wn   = (warp & 3) * 32;

    int a_row  = (lane & 7) | (lane & 8);
    int a_kof  = (lane >> 4) << 2;
    int b_rowp = ((lane >> 4) & 1) * 8 + (lane & 7);
    int b_kof  = (lane & 8) ? 4 : 0;

    float acc[4][4][4];
#pragma unroll
    for (int mf = 0; mf < 4; ++mf)
#pragma unroll
        for (int nf = 0; nf < 4; ++nf)
#pragma unroll
            for (int c = 0; c < 4; ++c) acc[mf][nf][c] = 0.f;

    auto load_stage = [&](int t) {
        uint32_t base = smem_u + (uint32_t)(t % STG) * STAGE_B;
#pragma unroll
        for (int i = 0; i < 4; ++i) {
            int idx = i*256 + tid;           // 0..1023
            int r   = idx >> 3;              // 0..127
            int c4  = (idx & 7) * 4;         // word offset 0..28
            int gr  = bm + r;
            bool p  = (gr < M);
            cp16(base + (uint32_t)(r*AST + c4)*4u,
                 A + (size_t)(p ? gr : 0)*CC + t*64 + c4*2, p);
            cp16(base + BOFF + (uint32_t)(r*BST + c4)*4u,
                 W2 + (size_t)(bn + r)*CW + t*32 + c4, true);
        }
        cp_commit();
    };

    load_stage(0);
    load_stage(1);

    for (int t = 0; t < NT; ++t) {
        if (t + 1 < NT) asm volatile("cp.async.wait_group 1;");
        else            asm volatile("cp.async.wait_group 0;");
        __syncthreads();
        if (t + 2 < NT) load_stage(t + 2);   // buffer (t-1)%3 free: all warps past it

        uint32_t base = smem_u + (uint32_t)(t % STG) * STAGE_B;
        uint32_t ab = base;
        uint32_t bb = base + BOFF;
#pragma unroll
        for (int s = 0; s < 4; ++s) {        // four k16 steps per stage
            int kw = s * 8;
            uint32_t af[4][4], bf[4][2];
#pragma unroll
            for (int mf = 0; mf < 4; ++mf)
                ldsm_x4(af[mf], ab + 4u*((wm + mf*16 + a_row)*AST + kw + a_kof));
#pragma unroll
            for (int nf2 = 0; nf2 < 2; ++nf2) {
                uint32_t q[4];
                ldsm_x4(q, bb + 4u*((wn + nf2*16 + b_rowp)*BST + kw + b_kof));
                bf[nf2*2  ][0] = q[0]; bf[nf2*2  ][1] = q[1];
                bf[nf2*2+1][0] = q[2]; bf[nf2*2+1][1] = q[3];
            }
#pragma unroll
            for (int nf = 0; nf < 4; ++nf)
#pragma unroll
                for (int mf = 0; mf < 4; ++mf)
                    mma16(acc[mf][nf], af[mf], bf[nf]);
        }
    }

#pragma unroll
    for (int mf = 0; mf < 4; ++mf) {
#pragma unroll
        for (int i = 0; i < 2; ++i) {
            int gr = bm + wm + mf*16 + g + i*8;
            if (gr >= M) continue;
#pragma unroll
            for (int nf = 0; nf < 4; ++nf) {
                int col = bn + wn + nf*8 + tg*2;
                if (Cf) {
                    float2 v;
                    v.x = acc[mf][nf][i*2 + 0] + bias[col];
                    v.y = acc[mf][nf][i*2 + 1] + bias[col+1];
                    *(float2*)&Cf[(size_t)gr*CC + col] = v;
                } else {
                    uint32_t w = packh2(acc[mf][nf][i*2 + 0], acc[mf][nf][i*2 + 1]);
                    *(uint32_t*)&Ch[(size_t)gr*CC + col] = w;
                }
            }
        }
    }
}

// Merged Q/K/V projection: flattened grid (1176 Q + 255 K + 255 V = 1686)
__global__ __launch_bounds__(256, 2)
void gemm_qkv(const __half* __restrict__ qc, const __half* __restrict__ kc,
              const __half* __restrict__ vc,
              const uint32_t* __restrict__ Wq2, const uint32_t* __restrict__ Wk2,
              const uint32_t* __restrict__ Wv2,
              __half* __restrict__ Qp, __half* __restrict__ Kp,
              __half* __restrict__ Vp)
{
    extern __shared__ __align__(16) char smem[];
    uint32_t smem_u = (uint32_t)__cvta_generic_to_shared(smem);
    int idx = blockIdx.x;
    const __half* A; const uint32_t* W2; __half* Ch; int M; int tile;
    if (idx < 1176)      { A = qc; W2 = Wq2; Ch = Qp; M = BB*TT; tile = idx; }
    else if (idx < 1431) { A = kc; W2 = Wk2; Ch = Kp; M = BB*TK; tile = idx - 1176; }
    else                 { A = vc; W2 = Wv2; Ch = Vp; M = BB*TK; tile = idx - 1431; }
    int mtiles = (M + 127) >> 7;
    int bm = (tile % mtiles) * 128;
    int bn = (tile / mtiles) * 128;
    gemm_body(A, W2, nullptr, Ch, nullptr, M, bm, bn, smem_u, threadIdx.x);
}

// Output projection (+bias, fp32 out)
__global__ __launch_bounds__(256, 2)
void gemm_out(const __half* __restrict__ Op, const uint32_t* __restrict__ Wo2,
              const float* __restrict__ bo, float* __restrict__ out)
{
    extern __shared__ __align__(16) char smem[];
    uint32_t smem_u = (uint32_t)__cvta_generic_to_shared(smem);
    int tile = blockIdx.x;
    int bm = (tile % 392) * 128;
    int bn = (tile / 392) * 128;
    gemm_body(Op, Wo2, bo, nullptr, out, BB*TT, bm, bn, smem_u, threadIdx.x);
}

// ---------------------------------------------------------------------------
// FP16 attention: cp.async staging, ldmatrix x4 fragments, register-resident
// S/P, lean softmax (mask only ni=21; exp2 with folded scale).
// ---------------------------------------------------------------------------
#define JP   176
#define NKC  22
#define QST  36
#define KST  36
#define VST  36

__global__ __launch_bounds__(256, 2)
void attn_f16(const __half* __restrict__ Q, const __half* __restrict__ K,
              const __half* __restrict__ V, __half* __restrict__ O)
{
    extern __shared__ uint32_t sm[];
    uint32_t* Qs = sm;
    uint32_t* Ks = Qs + 128*QST;
    uint32_t* Vs = Ks + JP*KST;

    int tid  = threadIdx.x;
    int warp = tid >> 5;
    int lane = tid & 31;
    int g    = lane >> 2;
    int tg   = lane & 3;
    int bh   = blockIdx.y;
    int b    = bh / NHEAD;
    int h    = bh - b * NHEAD;
    int row0 = blockIdx.x * 128;
    const float cE = rsqrtf((float)CC) * 1.44269504f;   // scale * log2(e)

    int a_row  = (lane & 7) | (lane & 8);
    int a_kof  = (lane >> 4) << 2;
    int b_rowp = ((lane >> 4) & 1) * 8 + (lane & 7);
    int b_kof  = (lane & 8) ? 4 : 0;

    uint32_t qb = (uint32_t)__cvta_generic_to_shared(Qs);
    uint32_t kb = (uint32_t)__cvta_generic_to_shared(Ks);
    uint32_t vb = (uint32_t)__cvta_generic_to_shared(Vs);

    const uint32_t* Qw = (const uint32_t*)Q + (size_t)b*TT*CW + h*32;
    const uint32_t* Kw = (const uint32_t*)K + (size_t)b*TK*CW + h*32;
    const uint32_t* Vw = (const uint32_t*)V + (size_t)b*TK*CW + h*32;

    for (int idx = tid; idx < 128*8; idx += 256) {
        int r = idx >> 3, c4 = (idx & 7) * 4;
        int gr = row0 + r;
        bool p = (gr < TT);
        cp16(qb + 4u*(r*QST + c4), Qw + (size_t)(p ? gr : 0)*CW + c4, p);
    }
    for (int idx = tid; idx < JP*8; idx += 256) {
        int j = idx >> 3, c4 = (idx & 7) * 4;
        bool p = (j < TK);
        int js = p ? j : 0;
        cp16(kb + 4u*(j*KST + c4), Kw + (size_t)js*CW + c4, p);
        cp16(vb + 4u*(j*VST + c4), Vw + (size_t)js*CW + c4, p);
    }
    cp_commit();
    asm volatile("cp.async.wait_group 0;");
    __syncthreads();

    int r0 = row0 + warp * 16;

    float p[NKC][4];
#pragma unroll
    for (int ni = 0; ni < NKC; ++ni)
#pragma unroll
        for (int c = 0; c < 4; ++c) p[ni][c] = 0.f;

#pragma unroll
    for (int kc = 0; kc < 4; ++kc) {
        int kw = kc * 8;
        uint32_t af[4];
        ldsm_x4(af, qb + 4u*((warp*16 + a_row)*QST + kw + a_kof));
#pragma unroll
        for (int np = 0; np < NKC/2; ++np) {
            uint32_t q[4];
            ldsm_x4(q, kb + 4u*((np*16 + b_rowp)*KST + kw + b_kof));
            uint32_t bf0[2] = { q[0], q[1] };
            uint32_t bf1[2] = { q[2], q[3] };
            mma16(p[np*2    ], af, bf0);
            mma16(p[np*2 + 1], af, bf1);
        }
    }

    // ---- mask (only ni=21 carries cols >= TK) ----
    // ni=21 cols: c0 = 168+2tg, c1 = 169+2tg. Valid only c0 when tg==0.
    if (tg == 0) {
        p[21][1] = -1e30f; p[21][3] = -1e30f;
    } else {
        p[21][0] = -1e30f; p[21][1] = -1e30f;
        p[21][2] = -1e30f; p[21][3] = -1e30f;
    }

    // ---- softmax: max on raw scores, exp2(fma) with folded scale ----
    float m0 = -1e30f, m1 = -1e30f;
#pragma unroll
    for (int ni = 0; ni < NKC; ++ni) {
        m0 = fmaxf(m0, fmaxf(p[ni][0], p[ni][1]));
        m1 = fmaxf(m1, fmaxf(p[ni][2], p[ni][3]));
    }
    m0 = fmaxf(m0, __shfl_xor_sync(~0u, m0, 1));
    m0 = fmaxf(m0, __shfl_xor_sync(~0u, m0, 2));
    m1 = fmaxf(m1, __shfl_xor_sync(~0u, m1, 1));
    m1 = fmaxf(m1, __shfl_xor_sync(~0u, m1, 2));
    float mc0 = m0 * cE, mc1 = m1 * cE;

    float s0 = 0.f, s1 = 0.f;
#pragma unroll
    for (int ni = 0; ni < NKC; ++ni) {
        p[ni][0] = exp2f(fmaf(p[ni][0], cE, -mc0));
        p[ni][1] = exp2f(fmaf(p[ni][1], cE, -mc0));
        p[ni][2] = exp2f(fmaf(p[ni][2], cE, -mc1));
        p[ni][3] = exp2f(fmaf(p[ni][3], cE, -mc1));
        s0 += p[ni][0] + p[ni][1];
        s1 += p[ni][2] + p[ni][3];
    }
    s0 += __shfl_xor_sync(~0u, s0, 1);
    s0 += __shfl_xor_sync(~0u, s0, 2);
    s1 += __shfl_xor_sync(~0u, s1, 1);
    s1 += __shfl_xor_sync(~0u, s1, 2);
    float i0 = 1.f / s0, i1 = 1.f / s1;

    uint32_t p2[2*NKC];
#pragma unroll
    for (int ni = 0; ni < NKC; ++ni) {
        p2[2*ni    ] = packh2(p[ni][0]*i0, p[ni][1]*i0);
        p2[2*ni + 1] = packh2(p[ni][2]*i1, p[ni][3]*i1);
    }

    float oacc[8][4];
#pragma unroll
    for (int nf = 0; nf < 8; ++nf)
#pragma unroll
        for (int c = 0; c < 4; ++c) oacc[nf][c] = 0.f;

#pragma unroll
    for (int kc = 0; kc < 11; ++kc) {
        uint32_t af[4];
        af[0] = p2[4*kc    ];
        af[1] = p2[4*kc + 1];
        af[2] = p2[4*kc + 2];
        af[3] = p2[4*kc + 3];
        int jr = kc * 16;
#pragma unroll
        for (int np = 0; np < 4; ++np) {
            uint32_t q[4];
            ldsm_x4t(q, vb + 4u*((jr + a_row)*VST + (np*2 + (lane >> 4))*4));
            uint32_t bf0[2] = { q[0], q[1] };
            uint32_t bf1[2] = { q[2], q[3] };
            mma16(oacc[np*2    ], af, bf0);
            mma16(oacc[np*2 + 1], af, bf1);
        }
    }

#pragma unroll
    for (int nf = 0; nf < 8; ++nf) {
#pragma unroll
        for (int i = 0; i < 2; ++i) {
            int gr = r0 + g + i*8;
            if (gr >= TT) continue;
            int col = h*DD + nf*8 + tg*2;
            uint32_t w = packh2(oacc[nf][i*2 + 0], oacc[nf][i*2 + 1]);
            *(uint32_t*)&O[((size_t)b*TT + gr)*CC + col] = w;
        }
    }
}

static const int ATTN_SMEM = (128*QST + JP*KST + JP*VST) * (int)sizeof(uint32_t); // 69120
static const int GEMM_SMEM = STG * (int)STAGE_B;   // 110592

extern "C" void kernel_launch(void* const* d_in, const int* in_sizes, int n_in,
                              void* d_out, int out_size)
{
    (void)in_sizes; (void)n_in; (void)out_size;
    const float* x   = (const float*)d_in[0];
    const float* wq  = (const float*)d_in[1];
    const float* qg  = (const float*)d_in[2];
    const float* qb  = (const float*)d_in[3];
    const float* qm  = (const float*)d_in[4];
    const float* qv  = (const float*)d_in[5];
    const float* wk  = (const float*)d_in[6];
    const float* kg  = (const float*)d_in[7];
    const float* kb  = (const float*)d_in[8];
    const float* km  = (const float*)d_in[9];
    const float* kv_ = (const float*)d_in[10];
    const float* wv  = (const float*)d_in[11];
    const float* vg  = (const float*)d_in[12];
    const float* vb  = (const float*)d_in[13];
    const float* vm  = (const float*)d_in[14];
    const float* vv_ = (const float*)d_in[15];
    const float* Wq  = (const float*)d_in[16];
    const float* Wk  = (const float*)d_in[17];
    const float* Wv  = (const float*)d_in[18];
    const float* Wo  = (const float*)d_in[19];
    const float* bo  = (const float*)d_in[20];
    float* out = (float*)d_out;

    __half *qc, *kc, *vc, *Qp, *Kp, *Vp, *Op;
    uint32_t *Wqt, *Wkt, *Wvt, *Wot;
    cudaGetSymbolAddress((void**)&qc, g_qc);
    cudaGetSymbolAddress((void**)&kc, g_kc);
    cudaGetSymbolAddress((void**)&vc, g_vc);
    cudaGetSymbolAddress((void**)&Qp, g_Q);
    cudaGetSymbolAddress((void**)&Kp, g_K);
    cudaGetSymbolAddress((void**)&Vp, g_V);
    cudaGetSymbolAddress((void**)&Op, g_O);
    cudaGetSymbolAddress((void**)&Wqt, g_Wqt);
    cudaGetSymbolAddress((void**)&Wkt, g_Wkt);
    cudaGetSymbolAddress((void**)&Wvt, g_Wvt);
    cudaGetSymbolAddress((void**)&Wot, g_Wot);

    // 0. weight conversion
    dim3 wg(CC/32, CC/32, 4);
    cvt_weights<<<wg, dim3(32,32)>>>(Wq, Wk, Wv, Wo);

    // 1. fused conv projections
    dwbn_fused<<<BB*HH, CC>>>(x, wq, qg, qb, qm, qv,
                              wk, kg, kb, km, kv_,
                              wv, vg, vb, vm, vv_, qc, kc, vc);

    // 2. merged Q/K/V dense projections
    cudaFuncSetAttribute(gemm_qkv, cudaFuncAttributeMaxDynamicSharedMemorySize, GEMM_SMEM);
    cudaFuncSetAttribute(gemm_out, cudaFuncAttributeMaxDynamicSharedMemorySize, GEMM_SMEM);
    gemm_qkv<<<1686, 256, GEMM_SMEM>>>(qc, kc, vc, Wqt, Wkt, Wvt, Qp, Kp, Vp);

    // 3. attention
    cudaFuncSetAttribute(attn_f16, cudaFuncAttributeMaxDynamicSharedMemorySize, ATTN_SMEM);
    dim3 ga((TT + 127)/128, BB*NHEAD);   // 7 x 384
    attn_f16<<<ga, 256, ATTN_SMEM>>>(Qp, Kp, Vp, Op);

    // 4. output projection (+bias, fp32 out)
    gemm_out<<<1176, 256, GEMM_SMEM>>>(Op, Wot, bo, out);
}

// round 12
// speedup vs baseline: 1.0464x; 1.0464x over previous
#include <cuda_runtime.h>
#include <cuda_fp16.h>
#include <math.h>
#include <stdint.h>

// Problem constants
#define BB   64
#define HH   28
#define WW   28
#define CC   384
#define TT   784      // HH*WW
#define HK   13       // (28-3)/2+1
#define TK   169      // 13*13
#define NHEAD 6
#define DD   64
#define EPSV 1e-3f
#define CW   (CC/2)   // 192 half2-words per row

// Scratch (device globals). Activations fp16; weights k-paired [n][k/2].
__device__ __half  g_qc[(size_t)BB*TT*CC];
__device__ __half  g_kc[(size_t)BB*TK*CC];
__device__ __half  g_vc[(size_t)BB*TK*CC];
__device__ __half  g_Q [(size_t)BB*TT*CC];
__device__ __half  g_K [(size_t)BB*TK*CC];
__device__ __half  g_V [(size_t)BB*TK*CC];
__device__ __half  g_O [(size_t)BB*TT*CC];
__device__ uint32_t g_Wqt[(size_t)CC*CW];
__device__ uint32_t g_Wkt[(size_t)CC*CW];
__device__ uint32_t g_Wvt[(size_t)CC*CW];
__device__ uint32_t g_Wot[(size_t)CC*CW];

// ---------------------------------------------------------------------------
// helpers
// ---------------------------------------------------------------------------
__device__ __forceinline__ uint32_t packh2(float a, float b) {
    __half2 h = __floats2half2_rn(a, b);
    return *reinterpret_cast<uint32_t*>(&h);
}

__device__ __forceinline__ void mma16(float* c, const uint32_t* a, const uint32_t* b) {
    asm volatile(
        "mma.sync.aligned.m16n8k16.row.col.f32.f16.f16.f32 "
        "{%0,%1,%2,%3}, {%4,%5,%6,%7}, {%8,%9}, {%0,%1,%2,%3};"
        : "+f"(c[0]), "+f"(c[1]), "+f"(c[2]), "+f"(c[3])
        : "r"(a[0]), "r"(a[1]), "r"(a[2]), "r"(a[3]), "r"(b[0]), "r"(b[1]));
}

__device__ __forceinline__ void ldsm_x4(uint32_t* r, uint32_t addr) {
    asm volatile("ldmatrix.sync.aligned.m8n8.x4.shared.b16 {%0,%1,%2,%3}, [%4];"
                 : "=r"(r[0]), "=r"(r[1]), "=r"(r[2]), "=r"(r[3]) : "r"(addr));
}
__device__ __forceinline__ void ldsm_x4t(uint32_t* r, uint32_t addr) {
    asm volatile("ldmatrix.sync.aligned.m8n8.x4.trans.shared.b16 {%0,%1,%2,%3}, [%4];"
                 : "=r"(r[0]), "=r"(r[1]), "=r"(r[2]), "=r"(r[3]) : "r"(addr));
}

__device__ __forceinline__ void cp16(uint32_t dst_smem, const void* src, bool pred) {
    int sz = pred ? 16 : 0;   // sz=0 -> 16B zero-fill
    asm volatile("cp.async.ca.shared.global [%0], [%1], 16, %2;"
                 :: "r"(dst_smem), "l"(src), "r"(sz));
}
__device__ __forceinline__ void cp_commit() { asm volatile("cp.async.commit_group;"); }

// ---------------------------------------------------------------------------
// Weight conversion: fp32 [k][n] -> fp16 k-paired [n][k/2] words. One-shot.
// ---------------------------------------------------------------------------
__global__ void cvt_weights(const float* __restrict__ Wq, const float* __restrict__ Wk,
                            const float* __restrict__ Wv, const float* __restrict__ Wo)
{
    __shared__ float tile[32][33];
    const float* W = (blockIdx.z == 0) ? Wq : (blockIdx.z == 1) ? Wk
                   : (blockIdx.z == 2) ? Wv : Wo;
    uint32_t* out = (blockIdx.z == 0) ? g_Wqt : (blockIdx.z == 1) ? g_Wkt
                  : (blockIdx.z == 2) ? g_Wvt : g_Wot;
    int k0 = blockIdx.x * 32, n0 = blockIdx.y * 32;
    int tx = threadIdx.x, ty = threadIdx.y;
    tile[ty][tx] = W[(size_t)(k0 + ty)*CC + n0 + tx];
    __syncthreads();
    if (tx < 16)
        out[(size_t)(n0 + ty)*CW + (k0 >> 1) + tx] =
            packh2(tile[2*tx][ty], tile[2*tx + 1][ty]);
}

// ---------------------------------------------------------------------------
// Fused depthwise 3x3 conv + BN (q stride1 SAME; k,v stride2 VALID on odd rows)
// ---------------------------------------------------------------------------
__global__ __launch_bounds__(CC)
void dwbn_fused(const float* __restrict__ x,
                const float* __restrict__ wq, const float* __restrict__ qg,
                const float* __restrict__ qb, const float* __restrict__ qm,
                const float* __restrict__ qv,
                const float* __restrict__ wk, const float* __restrict__ kg,
                const float* __restrict__ kb, const float* __restrict__ km,
                const float* __restrict__ kvv,
                const float* __restrict__ wv, const float* __restrict__ vg,
                const float* __restrict__ vb, const float* __restrict__ vm,
                const float* __restrict__ vvv,
                __half* __restrict__ outq, __half* __restrict__ outk,
                __half* __restrict__ outv)
{
    int c = threadIdx.x;
    int by = blockIdx.x;
    int b  = by / HH;
    int y  = by - b * HH;
    bool kvrow = (y & 1) && (y <= 2*(HK-1) + 1);
    int yk = y >> 1;

    float Wq9[9], Wk9[9], Wv9[9];
#pragma unroll
    for (int i = 0; i < 9; ++i) Wq9[i] = wq[i*CC + c];
    float scq = qg[c] * rsqrtf(qv[c] + EPSV);
    float shq = qb[c] - scq * qm[c];
    float sck = 0.f, shk = 0.f, scv = 0.f, shv = 0.f;
    if (kvrow) {
#pragma unroll
        for (int i = 0; i < 9; ++i) { Wk9[i] = wk[i*CC + c]; Wv9[i] = wv[i*CC + c]; }
        sck = kg[c] * rsqrtf(kvv[c] + EPSV);
        shk = kb[c] - sck * km[c];
        scv = vg[c] * rsqrtf(vvv[c] + EPSV);
        shv = vb[c] - scv * vm[c];
    }

    const float* xr0 = x + ((size_t)b*TT + (y-1)*WW)*CC + c;
    const float* xr1 = x + ((size_t)b*TT + (y  )*WW)*CC + c;
    const float* xr2 = x + ((size_t)b*TT + (y+1)*WW)*CC + c;
    bool ok0 = (y > 0), ok2 = (y < HH-1);

    __half* oq  = outq + ((size_t)b*TT + y*WW)*CC + c;
    __half* ok_ = outk + ((size_t)b*TK + yk*HK)*CC + c;
    __half* ov_ = outv + ((size_t)b*TK + yk*HK)*CC + c;

    float win[3][3];
#pragma unroll
    for (int dx = 0; dx < 3; ++dx)
#pragma unroll
        for (int dy = 0; dy < 3; ++dy) win[dx][dy] = 0.f;

    for (int col = 0; col <= WW; ++col) {
        if (col < WW) {
            size_t off = (size_t)col * CC;
            win[2][0] = ok0 ? xr0[off] : 0.f;
            win[2][1] = xr1[off];
            win[2][2] = ok2 ? xr2[off] : 0.f;
        } else {
            win[2][0] = win[2][1] = win[2][2] = 0.f;
        }

        if (col >= 1) {
            int j = col - 1;
            float acc = 0.f;
#pragma unroll
            for (int dy = 0; dy < 3; ++dy)
#pragma unroll
                for (int dx = 0; dx < 3; ++dx)
                    acc += win[dx][dy] * Wq9[dy*3 + dx];
            oq[(size_t)j*CC] = __float2half_rn(scq * acc + shq);

            if (kvrow && col >= 2 && !(col & 1) && col <= 2*(HK-1) + 2) {
                int xk = (col - 2) >> 1;
                float ak = 0.f, av = 0.f;
#pragma unroll
                for (int dy = 0; dy < 3; ++dy)
#pragma unroll
                    for (int dx = 0; dx < 3; ++dx) {
                        float xv = win[dx][dy];
                        ak += xv * Wk9[dy*3 + dx];
                        av += xv * Wv9[dy*3 + dx];
                    }
                ok_[(size_t)xk*CC] = __float2half_rn(sck * ak + shk);
                ov_[(size_t)xk*CC] = __float2half_rn(scv * av + shv);
            }
        }
#pragma unroll
        for (int dy = 0; dy < 3; ++dy) {
            win[0][dy] = win[1][dy];
            win[1][dy] = win[2][dy];
        }
    }
}

// ---------------------------------------------------------------------------
// FP16 GEMM body (R10 config): BK=32 halves, 3-stage cp.async, ONE
// syncthreads per K-iter (12 iters). 256 threads, block 128x128, warp 64x32.
// Stage = 20480B; 3 stages = 61440B dyn smem.
// ---------------------------------------------------------------------------
#define AST 20
#define BST 20
#define NT  12           // 384/32
#define STG 3
#define STAGE_B 20480u
#define BOFF  10240u

__device__ __forceinline__ void gemm_body(
    const __half* __restrict__ A, const uint32_t* __restrict__ W2,
    const float* __restrict__ bias, __half* __restrict__ Ch,
    float* __restrict__ Cf, int M, int bm, int bn, uint32_t smem_u, int tid)
{
    int warp = tid >> 5;
    int lane = tid & 31;
    int g    = lane >> 2;
    int tg   = lane & 3;
    int wm   = (warp >> 2) * 64;
    int wn   = (warp & 3) * 32;

    int l_r = tid >> 2;
    int l_q = (tid & 3) * 4;

    int a_row  = (lane & 7) | (lane & 8);
    int a_kof  = (lane >> 4) << 2;
    int b_rowp = ((lane >> 4) & 1) * 8 + (lane & 7);
    int b_kof  = (lane & 8) ? 4 : 0;

    float acc[4][4][4];
#pragma unroll
    for (int mf = 0; mf < 4; ++mf)
#pragma unroll
        for (int nf = 0; nf < 4; ++nf)
#pragma unroll
            for (int c = 0; c < 4; ++c) acc[mf][nf][c] = 0.f;

    auto load_stage = [&](int t) {
        uint32_t base = smem_u + (uint32_t)(t % STG) * STAGE_B;
#pragma unroll
        for (int i = 0; i < 2; ++i) {
            int r  = i*64 + l_r;
            int gr = bm + r;
            bool p = (gr < M);
            cp16(base + (uint32_t)(r*AST + l_q)*4u,
                 A + (size_t)(p ? gr : 0)*CC + t*32 + l_q*2, p);
        }
#pragma unroll
        for (int i = 0; i < 2; ++i) {
            int n = i*64 + l_r;
            cp16(base + BOFF + (uint32_t)(n*BST + l_q)*4u,
                 W2 + (size_t)(bn + n)*CW + t*16 + l_q, true);
        }
        cp_commit();
    };

    load_stage(0);
    load_stage(1);

    for (int t = 0; t < NT; ++t) {
        if (t + 1 < NT) asm volatile("cp.async.wait_group 1;");
        else            asm volatile("cp.async.wait_group 0;");
        __syncthreads();
        if (t + 2 < NT) load_stage(t + 2);

        uint32_t base = smem_u + (uint32_t)(t % STG) * STAGE_B;
        uint32_t ab = base;
        uint32_t bb = base + BOFF;
#pragma unroll
        for (int s = 0; s < 2; ++s) {
            int kw = s * 8;
            uint32_t af[4][4], bf[4][2];
#pragma unroll
            for (int mf = 0; mf < 4; ++mf)
                ldsm_x4(af[mf], ab + 4u*((wm + mf*16 + a_row)*AST + kw + a_kof));
#pragma unroll
            for (int nf2 = 0; nf2 < 2; ++nf2) {
                uint32_t q[4];
                ldsm_x4(q, bb + 4u*((wn + nf2*16 + b_rowp)*BST + kw + b_kof));
                bf[nf2*2  ][0] = q[0]; bf[nf2*2  ][1] = q[1];
                bf[nf2*2+1][0] = q[2]; bf[nf2*2+1][1] = q[3];
            }
#pragma unroll
            for (int nf = 0; nf < 4; ++nf)
#pragma unroll
                for (int mf = 0; mf < 4; ++mf)
                    mma16(acc[mf][nf], af[mf], bf[nf]);
        }
    }

#pragma unroll
    for (int mf = 0; mf < 4; ++mf) {
#pragma unroll
        for (int i = 0; i < 2; ++i) {
            int gr = bm + wm + mf*16 + g + i*8;
            if (gr >= M) continue;
#pragma unroll
            for (int nf = 0; nf < 4; ++nf) {
                int col = bn + wn + nf*8 + tg*2;
                if (Cf) {
                    float2 v;
                    v.x = acc[mf][nf][i*2 + 0] + bias[col];
                    v.y = acc[mf][nf][i*2 + 1] + bias[col+1];
                    *(float2*)&Cf[(size_t)gr*CC + col] = v;
                } else {
                    uint32_t w = packh2(acc[mf][nf][i*2 + 0], acc[mf][nf][i*2 + 1]);
                    *(uint32_t*)&Ch[(size_t)gr*CC + col] = w;
                }
            }
        }
    }
}

// Merged Q/K/V projection: flattened grid (1176 Q + 255 K + 255 V = 1686)
__global__ __launch_bounds__(256, 2)
void gemm_qkv(const __half* __restrict__ qc, const __half* __restrict__ kc,
              const __half* __restrict__ vc,
              const uint32_t* __restrict__ Wq2, const uint32_t* __restrict__ Wk2,
              const uint32_t* __restrict__ Wv2,
              __half* __restrict__ Qp, __half* __restrict__ Kp,
              __half* __restrict__ Vp)
{
    extern __shared__ __align__(16) char smem[];
    uint32_t smem_u = (uint32_t)__cvta_generic_to_shared(smem);
    int idx = blockIdx.x;
    const __half* A; const uint32_t* W2; __half* Ch; int M; int tile;
    if (idx < 1176)      { A = qc; W2 = Wq2; Ch = Qp; M = BB*TT; tile = idx; }
    else if (idx < 1431) { A = kc; W2 = Wk2; Ch = Kp; M = BB*TK; tile = idx - 1176; }
    else                 { A = vc; W2 = Wv2; Ch = Vp; M = BB*TK; tile = idx - 1431; }
    int mtiles = (M + 127) >> 7;
    int bm = (tile % mtiles) * 128;
    int bn = (tile / mtiles) * 128;
    gemm_body(A, W2, nullptr, Ch, nullptr, M, bm, bn, smem_u, threadIdx.x);
}

// Output projection (+bias, fp32 out)
__global__ __launch_bounds__(256, 2)
void gemm_out(const __half* __restrict__ Op, const uint32_t* __restrict__ Wo2,
              const float* __restrict__ bo, float* __restrict__ out)
{
    extern __shared__ __align__(16) char smem[];
    uint32_t smem_u = (uint32_t)__cvta_generic_to_shared(smem);
    int tile = blockIdx.x;
    int bm = (tile % 392) * 128;
    int bn = (tile / 392) * 128;
    gemm_body(Op, Wo2, bo, nullptr, out, BB*TT, bm, bn, smem_u, threadIdx.x);
}

// ---------------------------------------------------------------------------
// FP16 attention: spill-free softmax. Pack unnormalized exp into fp16 A-frags
// inside the exp loop (p[] dies immediately); normalize at the output store.
// ---------------------------------------------------------------------------
#define JP   176
#define NKC  22
#define QST  36
#define KST  36
#define VST  36

__global__ __launch_bounds__(256, 2)
void attn_f16(const __half* __restrict__ Q, const __half* __restrict__ K,
              const __half* __restrict__ V, __half* __restrict__ O)
{
    extern __shared__ uint32_t sm[];
    uint32_t* Qs = sm;
    uint32_t* Ks = Qs + 128*QST;
    uint32_t* Vs = Ks + JP*KST;

    int tid  = threadIdx.x;
    int warp = tid >> 5;
    int lane = tid & 31;
    int g    = lane >> 2;
    int tg   = lane & 3;
    int bh   = blockIdx.y;
    int b    = bh / NHEAD;
    int h    = bh - b * NHEAD;
    int row0 = blockIdx.x * 128;
    const float cE = rsqrtf((float)CC) * 1.44269504f;   // scale * log2(e)

    int a_row  = (lane & 7) | (lane & 8);
    int a_kof  = (lane >> 4) << 2;
    int b_rowp = ((lane >> 4) & 1) * 8 + (lane & 7);
    int b_kof  = (lane & 8) ? 4 : 0;

    uint32_t qb = (uint32_t)__cvta_generic_to_shared(Qs);
    uint32_t kb = (uint32_t)__cvta_generic_to_shared(Ks);
    uint32_t vb = (uint32_t)__cvta_generic_to_shared(Vs);

    const uint32_t* Qw = (const uint32_t*)Q + (size_t)b*TT*CW + h*32;
    const uint32_t* Kw = (const uint32_t*)K + (size_t)b*TK*CW + h*32;
    const uint32_t* Vw = (const uint32_t*)V + (size_t)b*TK*CW + h*32;

    for (int idx = tid; idx < 128*8; idx += 256) {
        int r = idx >> 3, c4 = (idx & 7) * 4;
        int gr = row0 + r;
        bool p = (gr < TT);
        cp16(qb + 4u*(r*QST + c4), Qw + (size_t)(p ? gr : 0)*CW + c4, p);
    }
    for (int idx = tid; idx < JP*8; idx += 256) {
        int j = idx >> 3, c4 = (idx & 7) * 4;
        bool p = (j < TK);
        int js = p ? j : 0;
        cp16(kb + 4u*(j*KST + c4), Kw + (size_t)js*CW + c4, p);
        cp16(vb + 4u*(j*VST + c4), Vw + (size_t)js*CW + c4, p);
    }
    cp_commit();
    asm volatile("cp.async.wait_group 0;");
    __syncthreads();

    int r0 = row0 + warp * 16;

    float p[NKC][4];
#pragma unroll
    for (int ni = 0; ni < NKC; ++ni)
#pragma unroll
        for (int c = 0; c < 4; ++c) p[ni][c] = 0.f;

#pragma unroll
    for (int kc = 0; kc < 4; ++kc) {
        int kw = kc * 8;
        uint32_t af[4];
        ldsm_x4(af, qb + 4u*((warp*16 + a_row)*QST + kw + a_kof));
#pragma unroll
        for (int np = 0; np < NKC/2; ++np) {
            uint32_t q[4];
            ldsm_x4(q, kb + 4u*((np*16 + b_rowp)*KST + kw + b_kof));
            uint32_t bf0[2] = { q[0], q[1] };
            uint32_t bf1[2] = { q[2], q[3] };
            mma16(p[np*2    ], af, bf0);
            mma16(p[np*2 + 1], af, bf1);
        }
    }

    // ---- mask (only ni=21 carries cols >= TK) ----
    if (tg == 0) {
        p[21][1] = -1e30f; p[21][3] = -1e30f;
    } else {
        p[21][0] = -1e30f; p[21][1] = -1e30f;
        p[21][2] = -1e30f; p[21][3] = -1e30f;
    }

    // ---- max reduce on raw scores ----
    float m0 = -1e30f, m1 = -1e30f;
#pragma unroll
    for (int ni = 0; ni < NKC; ++ni) {
        m0 = fmaxf(m0, fmaxf(p[ni][0], p[ni][1]));
        m1 = fmaxf(m1, fmaxf(p[ni][2], p[ni][3]));
    }
    m0 = fmaxf(m0, __shfl_xor_sync(~0u, m0, 1));
    m0 = fmaxf(m0, __shfl_xor_sync(~0u, m0, 2));
    m1 = fmaxf(m1, __shfl_xor_sync(~0u, m1, 1));
    m1 = fmaxf(m1, __shfl_xor_sync(~0u, m1, 2));
    float mc0 = m0 * cE, mc1 = m1 * cE;

    // ---- exp + pack UNNORMALIZED into fp16 frags (p dies here -> no spill) ----
    uint32_t p2[2*NKC];
    float s0 = 0.f, s1 = 0.f;
#pragma unroll
    for (int ni = 0; ni < NKC; ++ni) {
        float e0 = exp2f(fmaf(p[ni][0], cE, -mc0));
        float e1 = exp2f(fmaf(p[ni][1], cE, -mc0));
        float e2 = exp2f(fmaf(p[ni][2], cE, -mc1));
        float e3 = exp2f(fmaf(p[ni][3], cE, -mc1));
        s0 += e0 + e1;
        s1 += e2 + e3;
        p2[2*ni    ] = packh2(e0, e1);
        p2[2*ni + 1] = packh2(e2, e3);
    }
    s0 += __shfl_xor_sync(~0u, s0, 1);
    s0 += __shfl_xor_sync(~0u, s0, 2);
    s1 += __shfl_xor_sync(~0u, s1, 1);
    s1 += __shfl_xor_sync(~0u, s1, 2);
    float i0 = 1.f / s0, i1 = 1.f / s1;

    // ---- O = P V (unnormalized); normalize at store ----
    float oacc[8][4];
#pragma unroll
    for (int nf = 0; nf < 8; ++nf)
#pragma unroll
        for (int c = 0; c < 4; ++c) oacc[nf][c] = 0.f;

#pragma unroll
    for (int kc = 0; kc < 11; ++kc) {
        uint32_t af[4];
        af[0] = p2[4*kc    ];
        af[1] = p2[4*kc + 1];
        af[2] = p2[4*kc + 2];
        af[3] = p2[4*kc + 3];
        int jr = kc * 16;
#pragma unroll
        for (int np = 0; np < 4; ++np) {
            uint32_t q[4];
            ldsm_x4t(q, vb + 4u*((jr + a_row)*VST + (np*2 + (lane >> 4))*4));
            uint32_t bf0[2] = { q[0], q[1] };
            uint32_t bf1[2] = { q[2], q[3] };
            mma16(oacc[np*2    ], af, bf0);
            mma16(oacc[np*2 + 1], af, bf1);
        }
    }

#pragma unroll
    for (int nf = 0; nf < 8; ++nf) {
#pragma unroll
        for (int i = 0; i < 2; ++i) {
            int gr = r0 + g + i*8;
            if (gr >= TT) continue;
            float sc = i ? i1 : i0;
            int col = h*DD + nf*8 + tg*2;
            uint32_t w = packh2(oacc[nf][i*2 + 0] * sc, oacc[nf][i*2 + 1] * sc);
            *(uint32_t*)&O[((size_t)b*TT + gr)*CC + col] = w;
        }
    }
}

static const int ATTN_SMEM = (128*QST + JP*KST + JP*VST) * (int)sizeof(uint32_t); // 69120
static const int GEMM_SMEM = STG * (int)STAGE_B;   // 61440

extern "C" void kernel_launch(void* const* d_in, const int* in_sizes, int n_in,
                              void* d_out, int out_size)
{
    (void)in_sizes; (void)n_in; (void)out_size;
    const float* x   = (const float*)d_in[0];
    const float* wq  = (const float*)d_in[1];
    const float* qg  = (const float*)d_in[2];
    const float* qb  = (const float*)d_in[3];
    const float* qm  = (const float*)d_in[4];
    const float* qv  = (const float*)d_in[5];
    const float* wk  = (const float*)d_in[6];
    const float* kg  = (const float*)d_in[7];
    const float* kb  = (const float*)d_in[8];
    const float* km  = (const float*)d_in[9];
    const float* kv_ = (const float*)d_in[10];
    const float* wv  = (const float*)d_in[11];
    const float* vg  = (const float*)d_in[12];
    const float* vb  = (const float*)d_in[13];
    const float* vm  = (const float*)d_in[14];
    const float* vv_ = (const float*)d_in[15];
    const float* Wq  = (const float*)d_in[16];
    const float* Wk  = (const float*)d_in[17];
    const float* Wv  = (const float*)d_in[18];
    const float* Wo  = (const float*)d_in[19];
    const float* bo  = (const float*)d_in[20];
    float* out = (float*)d_out;

    __half *qc, *kc, *vc, *Qp, *Kp, *Vp, *Op;
    uint32_t *Wqt, *Wkt, *Wvt, *Wot;
    cudaGetSymbolAddress((void**)&qc, g_qc);
    cudaGetSymbolAddress((void**)&kc, g_kc);
    cudaGetSymbolAddress((void**)&vc, g_vc);
    cudaGetSymbolAddress((void**)&Qp, g_Q);
    cudaGetSymbolAddress((void**)&Kp, g_K);
    cudaGetSymbolAddress((void**)&Vp, g_V);
    cudaGetSymbolAddress((void**)&Op, g_O);
    cudaGetSymbolAddress((void**)&Wqt, g_Wqt);
    cudaGetSymbolAddress((void**)&Wkt, g_Wkt);
    cudaGetSymbolAddress((void**)&Wvt, g_Wvt);
    cudaGetSymbolAddress((void**)&Wot, g_Wot);

    // 0. weight conversion
    dim3 wg(CC/32, CC/32, 4);
    cvt_weights<<<wg, dim3(32,32)>>>(Wq, Wk, Wv, Wo);

    // 1. fused conv projections
    dwbn_fused<<<BB*HH, CC>>>(x, wq, qg, qb, qm, qv,
                              wk, kg, kb, km, kv_,
                              wv, vg, vb, vm, vv_, qc, kc, vc);

    // 2. merged Q/K/V dense projections
    cudaFuncSetAttribute(gemm_qkv, cudaFuncAttributeMaxDynamicSharedMemorySize, GEMM_SMEM);
    cudaFuncSetAttribute(gemm_out, cudaFuncAttributeMaxDynamicSharedMemorySize, GEMM_SMEM);
    gemm_qkv<<<1686, 256, GEMM_SMEM>>>(qc, kc, vc, Wqt, Wkt, Wvt, Qp, Kp, Vp);

    // 3. attention
    cudaFuncSetAttribute(attn_f16, cudaFuncAttributeMaxDynamicSharedMemorySize, ATTN_SMEM);
    dim3 ga((TT + 127)/128, BB*NHEAD);   // 7 x 384
    attn_f16<<<ga, 256, ATTN_SMEM>>>(Qp, Kp, Vp, Op);

    // 4. output projection (+bias, fp32 out)
    gemm_out<<<1176, 256, GEMM_SMEM>>>(Op, Wot, bo, out);
}

// round 13
// speedup vs baseline: 1.0788x; 1.0310x over previous
#include <cuda_runtime.h>
#include <cuda_fp16.h>
#include <math.h>
#include <stdint.h>

// Problem constants
#define BB   64
#define HH   28
#define WW   28
#define CC   384
#define TT   784      // HH*WW
#define HK   13       // (28-3)/2+1
#define TK   169      // 13*13
#define NHEAD 6
#define DD   64
#define EPSV 1e-3f
#define CW   (CC/2)   // 192 half2-words per row

// Scratch (device globals). Activations fp16; weights k-paired [n][k/2].
__device__ __half  g_qc[(size_t)BB*TT*CC];
__device__ __half  g_kc[(size_t)BB*TK*CC];
__device__ __half  g_vc[(size_t)BB*TK*CC];
__device__ __half  g_Q [(size_t)BB*TT*CC];
__device__ __half  g_K [(size_t)BB*TK*CC];
__device__ __half  g_V [(size_t)BB*TK*CC];
__device__ __half  g_O [(size_t)BB*TT*CC];
__device__ uint32_t g_Wqt[(size_t)CC*CW];
__device__ uint32_t g_Wkt[(size_t)CC*CW];
__device__ uint32_t g_Wvt[(size_t)CC*CW];
__device__ uint32_t g_Wot[(size_t)CC*CW];

// ---------------------------------------------------------------------------
// helpers
// ---------------------------------------------------------------------------
__device__ __forceinline__ uint32_t packh2(float a, float b) {
    __half2 h = __floats2half2_rn(a, b);
    return *reinterpret_cast<uint32_t*>(&h);
}

__device__ __forceinline__ void mma16(float* c, const uint32_t* a, const uint32_t* b) {
    asm volatile(
        "mma.sync.aligned.m16n8k16.row.col.f32.f16.f16.f32 "
        "{%0,%1,%2,%3}, {%4,%5,%6,%7}, {%8,%9}, {%0,%1,%2,%3};"
        : "+f"(c[0]), "+f"(c[1]), "+f"(c[2]), "+f"(c[3])
        : "r"(a[0]), "r"(a[1]), "r"(a[2]), "r"(a[3]), "r"(b[0]), "r"(b[1]));
}

__device__ __forceinline__ void ldsm_x4(uint32_t* r, uint32_t addr) {
    asm volatile("ldmatrix.sync.aligned.m8n8.x4.shared.b16 {%0,%1,%2,%3}, [%4];"
                 : "=r"(r[0]), "=r"(r[1]), "=r"(r[2]), "=r"(r[3]) : "r"(addr));
}
__device__ __forceinline__ void ldsm_x4t(uint32_t* r, uint32_t addr) {
    asm volatile("ldmatrix.sync.aligned.m8n8.x4.trans.shared.b16 {%0,%1,%2,%3}, [%4];"
                 : "=r"(r[0]), "=r"(r[1]), "=r"(r[2]), "=r"(r[3]) : "r"(addr));
}

__device__ __forceinline__ void cp16(uint32_t dst_smem, const void* src, bool pred) {
    int sz = pred ? 16 : 0;   // sz=0 -> 16B zero-fill
    asm volatile("cp.async.ca.shared.global [%0], [%1], 16, %2;"
                 :: "r"(dst_smem), "l"(src), "r"(sz));
}
__device__ __forceinline__ void cp_commit() { asm volatile("cp.async.commit_group;"); }

// ---------------------------------------------------------------------------
// Weight conversion: fp32 [k][n] -> fp16 k-paired [n][k/2] words. One-shot.
// ---------------------------------------------------------------------------
__global__ void cvt_weights(const float* __restrict__ Wq, const float* __restrict__ Wk,
                            const float* __restrict__ Wv, const float* __restrict__ Wo)
{
    __shared__ float tile[32][33];
    const float* W = (blockIdx.z == 0) ? Wq : (blockIdx.z == 1) ? Wk
                   : (blockIdx.z == 2) ? Wv : Wo;
    uint32_t* out = (blockIdx.z == 0) ? g_Wqt : (blockIdx.z == 1) ? g_Wkt
                  : (blockIdx.z == 2) ? g_Wvt : g_Wot;
    int k0 = blockIdx.x * 32, n0 = blockIdx.y * 32;
    int tx = threadIdx.x, ty = threadIdx.y;
    tile[ty][tx] = W[(size_t)(k0 + ty)*CC + n0 + tx];
    __syncthreads();
    if (tx < 16)
        out[(size_t)(n0 + ty)*CW + (k0 >> 1) + tx] =
            packh2(tile[2*tx][ty], tile[2*tx + 1][ty]);
}

// ---------------------------------------------------------------------------
// Fused depthwise 3x3 conv + BN (q stride1 SAME; k,v stride2 VALID on odd rows)
// ---------------------------------------------------------------------------
__global__ __launch_bounds__(CC)
void dwbn_fused(const float* __restrict__ x,
                const float* __restrict__ wq, const float* __restrict__ qg,
                const float* __restrict__ qb, const float* __restrict__ qm,
                const float* __restrict__ qv,
                const float* __restrict__ wk, const float* __restrict__ kg,
                const float* __restrict__ kb, const float* __restrict__ km,
                const float* __restrict__ kvv,
                const float* __restrict__ wv, const float* __restrict__ vg,
                const float* __restrict__ vb, const float* __restrict__ vm,
                const float* __restrict__ vvv,
                __half* __restrict__ outq, __half* __restrict__ outk,
                __half* __restrict__ outv)
{
    int c = threadIdx.x;
    int by = blockIdx.x;
    int b  = by / HH;
    int y  = by - b * HH;
    bool kvrow = (y & 1) && (y <= 2*(HK-1) + 1);
    int yk = y >> 1;

    float Wq9[9], Wk9[9], Wv9[9];
#pragma unroll
    for (int i = 0; i < 9; ++i) Wq9[i] = wq[i*CC + c];
    float scq = qg[c] * rsqrtf(qv[c] + EPSV);
    float shq = qb[c] - scq * qm[c];
    float sck = 0.f, shk = 0.f, scv = 0.f, shv = 0.f;
    if (kvrow) {
#pragma unroll
        for (int i = 0; i < 9; ++i) { Wk9[i] = wk[i*CC + c]; Wv9[i] = wv[i*CC + c]; }
        sck = kg[c] * rsqrtf(kvv[c] + EPSV);
        shk = kb[c] - sck * km[c];
        scv = vg[c] * rsqrtf(vvv[c] + EPSV);
        shv = vb[c] - scv * vm[c];
    }

    const float* xr0 = x + ((size_t)b*TT + (y-1)*WW)*CC + c;
    const float* xr1 = x + ((size_t)b*TT + (y  )*WW)*CC + c;
    const float* xr2 = x + ((size_t)b*TT + (y+1)*WW)*CC + c;
    bool ok0 = (y > 0), ok2 = (y < HH-1);

    __half* oq  = outq + ((size_t)b*TT + y*WW)*CC + c;
    __half* ok_ = outk + ((size_t)b*TK + yk*HK)*CC + c;
    __half* ov_ = outv + ((size_t)b*TK + yk*HK)*CC + c;

    float win[3][3];
#pragma unroll
    for (int dx = 0; dx < 3; ++dx)
#pragma unroll
        for (int dy = 0; dy < 3; ++dy) win[dx][dy] = 0.f;

    for (int col = 0; col <= WW; ++col) {
        if (col < WW) {
            size_t off = (size_t)col * CC;
            win[2][0] = ok0 ? xr0[off] : 0.f;
            win[2][1] = xr1[off];
            win[2][2] = ok2 ? xr2[off] : 0.f;
        } else {
            win[2][0] = win[2][1] = win[2][2] = 0.f;
        }

        if (col >= 1) {
            int j = col - 1;
            float acc = 0.f;
#pragma unroll
            for (int dy = 0; dy < 3; ++dy)
#pragma unroll
                for (int dx = 0; dx < 3; ++dx)
                    acc += win[dx][dy] * Wq9[dy*3 + dx];
            oq[(size_t)j*CC] = __float2half_rn(scq * acc + shq);

            if (kvrow && col >= 2 && !(col & 1) && col <= 2*(HK-1) + 2) {
                int xk = (col - 2) >> 1;
                float ak = 0.f, av = 0.f;
#pragma unroll
                for (int dy = 0; dy < 3; ++dy)
#pragma unroll
                    for (int dx = 0; dx < 3; ++dx) {
                        float xv = win[dx][dy];
                        ak += xv * Wk9[dy*3 + dx];
                        av += xv * Wv9[dy*3 + dx];
                    }
                ok_[(size_t)xk*CC] = __float2half_rn(sck * ak + shk);
                ov_[(size_t)xk*CC] = __float2half_rn(scv * av + shv);
            }
        }
#pragma unroll
        for (int dy = 0; dy < 3; ++dy) {
            win[0][dy] = win[1][dy];
            win[1][dy] = win[2][dy];
        }
    }
}

// ---------------------------------------------------------------------------
// FP16 GEMM body (R10 config): BK=32 halves, 3-stage cp.async, ONE
// syncthreads per K-iter (12 iters). 256 threads, block 128x128, warp 64x32.
// ---------------------------------------------------------------------------
#define AST 20
#define BST 20
#define NT  12
#define STG 3
#define STAGE_B 20480u
#define BOFF  10240u

__device__ __forceinline__ void gemm_body(
    const __half* __restrict__ A, const uint32_t* __restrict__ W2,
    const float* __restrict__ bias, __half* __restrict__ Ch,
    float* __restrict__ Cf, int M, int bm, int bn, uint32_t smem_u, int tid)
{
    int warp = tid >> 5;
    int lane = tid & 31;
    int g    = lane >> 2;
    int tg   = lane & 3;
    int wm   = (warp >> 2) * 64;
    int wn   = (warp & 3) * 32;

    int l_r = tid >> 2;
    int l_q = (tid & 3) * 4;

    int a_row  = (lane & 7) | (lane & 8);
    int a_kof  = (lane >> 4) << 2;
    int b_rowp = ((lane >> 4) & 1) * 8 + (lane & 7);
    int b_kof  = (lane & 8) ? 4 : 0;

    float acc[4][4][4];
#pragma unroll
    for (int mf = 0; mf < 4; ++mf)
#pragma unroll
        for (int nf = 0; nf < 4; ++nf)
#pragma unroll
            for (int c = 0; c < 4; ++c) acc[mf][nf][c] = 0.f;

    auto load_stage = [&](int t) {
        uint32_t base = smem_u + (uint32_t)(t % STG) * STAGE_B;
#pragma unroll
        for (int i = 0; i < 2; ++i) {
            int r  = i*64 + l_r;
            int gr = bm + r;
            bool p = (gr < M);
            cp16(base + (uint32_t)(r*AST + l_q)*4u,
                 A + (size_t)(p ? gr : 0)*CC + t*32 + l_q*2, p);
        }
#pragma unroll
        for (int i = 0; i < 2; ++i) {
            int n = i*64 + l_r;
            cp16(base + BOFF + (uint32_t)(n*BST + l_q)*4u,
                 W2 + (size_t)(bn + n)*CW + t*16 + l_q, true);
        }
        cp_commit();
    };

    load_stage(0);
    load_stage(1);

    for (int t = 0; t < NT; ++t) {
        if (t + 1 < NT) asm volatile("cp.async.wait_group 1;");
        else            asm volatile("cp.async.wait_group 0;");
        __syncthreads();
        if (t + 2 < NT) load_stage(t + 2);

        uint32_t base = smem_u + (uint32_t)(t % STG) * STAGE_B;
        uint32_t ab = base;
        uint32_t bb = base + BOFF;
#pragma unroll
        for (int s = 0; s < 2; ++s) {
            int kw = s * 8;
            uint32_t af[4][4], bf[4][2];
#pragma unroll
            for (int mf = 0; mf < 4; ++mf)
                ldsm_x4(af[mf], ab + 4u*((wm + mf*16 + a_row)*AST + kw + a_kof));
#pragma unroll
            for (int nf2 = 0; nf2 < 2; ++nf2) {
                uint32_t q[4];
                ldsm_x4(q, bb + 4u*((wn + nf2*16 + b_rowp)*BST + kw + b_kof));
                bf[nf2*2  ][0] = q[0]; bf[nf2*2  ][1] = q[1];
                bf[nf2*2+1][0] = q[2]; bf[nf2*2+1][1] = q[3];
            }
#pragma unroll
            for (int nf = 0; nf < 4; ++nf)
#pragma unroll
                for (int mf = 0; mf < 4; ++mf)
                    mma16(acc[mf][nf], af[mf], bf[nf]);
        }
    }

#pragma unroll
    for (int mf = 0; mf < 4; ++mf) {
#pragma unroll
        for (int i = 0; i < 2; ++i) {
            int gr = bm + wm + mf*16 + g + i*8;
            if (gr >= M) continue;
#pragma unroll
            for (int nf = 0; nf < 4; ++nf) {
                int col = bn + wn + nf*8 + tg*2;
                if (Cf) {
                    float2 v;
                    v.x = acc[mf][nf][i*2 + 0] + bias[col];
                    v.y = acc[mf][nf][i*2 + 1] + bias[col+1];
                    *(float2*)&Cf[(size_t)gr*CC + col] = v;
                } else {
                    uint32_t w = packh2(acc[mf][nf][i*2 + 0], acc[mf][nf][i*2 + 1]);
                    *(uint32_t*)&Ch[(size_t)gr*CC + col] = w;
                }
            }
        }
    }
}

// Merged Q/K/V projection: flattened grid (1176 Q + 255 K + 255 V = 1686)
__global__ __launch_bounds__(256, 2)
void gemm_qkv(const __half* __restrict__ qc, const __half* __restrict__ kc,
              const __half* __restrict__ vc,
              const uint32_t* __restrict__ Wq2, const uint32_t* __restrict__ Wk2,
              const uint32_t* __restrict__ Wv2,
              __half* __restrict__ Qp, __half* __restrict__ Kp,
              __half* __restrict__ Vp)
{
    extern __shared__ __align__(16) char smem[];
    uint32_t smem_u = (uint32_t)__cvta_generic_to_shared(smem);
    int idx = blockIdx.x;
    const __half* A; const uint32_t* W2; __half* Ch; int M; int tile;
    if (idx < 1176)      { A = qc; W2 = Wq2; Ch = Qp; M = BB*TT; tile = idx; }
    else if (idx < 1431) { A = kc; W2 = Wk2; Ch = Kp; M = BB*TK; tile = idx - 1176; }
    else                 { A = vc; W2 = Wv2; Ch = Vp; M = BB*TK; tile = idx - 1431; }
    int mtiles = (M + 127) >> 7;
    int bm = (tile % mtiles) * 128;
    int bn = (tile / mtiles) * 128;
    gemm_body(A, W2, nullptr, Ch, nullptr, M, bm, bn, smem_u, threadIdx.x);
}

// Output projection (+bias, fp32 out)
__global__ __launch_bounds__(256, 2)
void gemm_out(const __half* __restrict__ Op, const uint32_t* __restrict__ Wo2,
              const float* __restrict__ bo, float* __restrict__ out)
{
    extern __shared__ __align__(16) char smem[];
    uint32_t smem_u = (uint32_t)__cvta_generic_to_shared(smem);
    int tile = blockIdx.x;
    int bm = (tile % 392) * 128;
    int bn = (tile / 392) * 128;
    gemm_body(Op, Wo2, bo, nullptr, out, BB*TT, bm, bn, smem_u, threadIdx.x);
}

// ---------------------------------------------------------------------------
// FP16 attention: 224 threads (7 warps x 16 rows = 112 rows/block, exact:
// 7 blocks x 112 = 784, no row padding/predicates). Spill-free softmax,
// software-pipelined PV ldmatrix.
// ---------------------------------------------------------------------------
#define JP   176
#define NKC  22
#define QST  36
#define KST  36
#define VST  36
#define ATHR 224

__global__ __launch_bounds__(ATHR, 2)
void attn_f16(const __half* __restrict__ Q, const __half* __restrict__ K,
              const __half* __restrict__ V, __half* __restrict__ O)
{
    extern __shared__ uint32_t sm[];
    uint32_t* Qs = sm;                    // 112 x 36
    uint32_t* Ks = Qs + 112*QST;          // 176 x 36
    uint32_t* Vs = Ks + JP*KST;           // 176 x 36

    int tid  = threadIdx.x;
    int warp = tid >> 5;
    int lane = tid & 31;
    int g    = lane >> 2;
    int tg   = lane & 3;
    int bh   = blockIdx.y;
    int b    = bh / NHEAD;
    int h    = bh - b * NHEAD;
    int row0 = blockIdx.x * 112;
    const float cE = rsqrtf((float)CC) * 1.44269504f;   // scale * log2(e)

    int a_row  = (lane & 7) | (lane & 8);
    int a_kof  = (lane >> 4) << 2;
    int b_rowp = ((lane >> 4) & 1) * 8 + (lane & 7);
    int b_kof  = (lane & 8) ? 4 : 0;

    uint32_t qb = (uint32_t)__cvta_generic_to_shared(Qs);
    uint32_t kb = (uint32_t)__cvta_generic_to_shared(Ks);
    uint32_t vb = (uint32_t)__cvta_generic_to_shared(Vs);

    const uint32_t* Qw = (const uint32_t*)Q + (size_t)b*TT*CW + h*32;
    const uint32_t* Kw = (const uint32_t*)K + (size_t)b*TK*CW + h*32;
    const uint32_t* Vw = (const uint32_t*)V + (size_t)b*TK*CW + h*32;

    // Stage Q: 112 rows x 8 chunks = 896 = 4 * 224 (exact, unpredicated rows)
#pragma unroll
    for (int i = 0; i < 4; ++i) {
        int idx = i*ATHR + tid;
        int r = idx >> 3, c4 = (idx & 7) * 4;
        cp16(qb + 4u*(r*QST + c4), Qw + (size_t)(row0 + r)*CW + c4, true);
    }
    // Stage K and V (176 rows x 8 chunks), zero-fill j >= TK
    for (int idx = tid; idx < JP*8; idx += ATHR) {
        int j = idx >> 3, c4 = (idx & 7) * 4;
        bool p = (j < TK);
        int js = p ? j : 0;
        cp16(kb + 4u*(j*KST + c4), Kw + (size_t)js*CW + c4, p);
        cp16(vb + 4u*(j*VST + c4), Vw + (size_t)js*CW + c4, p);
    }
    cp_commit();
    asm volatile("cp.async.wait_group 0;");
    __syncthreads();

    int r0 = row0 + warp * 16;

    float p[NKC][4];
#pragma unroll
    for (int ni = 0; ni < NKC; ++ni)
#pragma unroll
        for (int c = 0; c < 4; ++c) p[ni][c] = 0.f;

#pragma unroll
    for (int kc = 0; kc < 4; ++kc) {
        int kw = kc * 8;
        uint32_t af[4];
        ldsm_x4(af, qb + 4u*((warp*16 + a_row)*QST + kw + a_kof));
#pragma unroll
        for (int np = 0; np < NKC/2; ++np) {
            uint32_t q[4];
            ldsm_x4(q, kb + 4u*((np*16 + b_rowp)*KST + kw + b_kof));
            uint32_t bf0[2] = { q[0], q[1] };
            uint32_t bf1[2] = { q[2], q[3] };
            mma16(p[np*2    ], af, bf0);
            mma16(p[np*2 + 1], af, bf1);
        }
    }

    // ---- mask (only ni=21 carries cols >= TK) ----
    if (tg == 0) {
        p[21][1] = -1e30f; p[21][3] = -1e30f;
    } else {
        p[21][0] = -1e30f; p[21][1] = -1e30f;
        p[21][2] = -1e30f; p[21][3] = -1e30f;
    }

    // ---- max reduce ----
    float m0 = -1e30f, m1 = -1e30f;
#pragma unroll
    for (int ni = 0; ni < NKC; ++ni) {
        m0 = fmaxf(m0, fmaxf(p[ni][0], p[ni][1]));
        m1 = fmaxf(m1, fmaxf(p[ni][2], p[ni][3]));
    }
    m0 = fmaxf(m0, __shfl_xor_sync(~0u, m0, 1));
    m0 = fmaxf(m0, __shfl_xor_sync(~0u, m0, 2));
    m1 = fmaxf(m1, __shfl_xor_sync(~0u, m1, 1));
    m1 = fmaxf(m1, __shfl_xor_sync(~0u, m1, 2));
    float mc0 = m0 * cE, mc1 = m1 * cE;

    // ---- exp + pack unnormalized (p dies here) ----
    uint32_t p2[2*NKC];
    float s0 = 0.f, s1 = 0.f;
#pragma unroll
    for (int ni = 0; ni < NKC; ++ni) {
        float e0 = exp2f(fmaf(p[ni][0], cE, -mc0));
        float e1 = exp2f(fmaf(p[ni][1], cE, -mc0));
        float e2 = exp2f(fmaf(p[ni][2], cE, -mc1));
        float e3 = exp2f(fmaf(p[ni][3], cE, -mc1));
        s0 += e0 + e1;
        s1 += e2 + e3;
        p2[2*ni    ] = packh2(e0, e1);
        p2[2*ni + 1] = packh2(e2, e3);
    }
    s0 += __shfl_xor_sync(~0u, s0, 1);
    s0 += __shfl_xor_sync(~0u, s0, 2);
    s1 += __shfl_xor_sync(~0u, s1, 1);
    s1 += __shfl_xor_sync(~0u, s1, 2);
    float i0 = 1.f / s0, i1 = 1.f / s1;

    // ---- O = P V : flat 44-iter loop, V ldmatrix pipelined 1 ahead ----
    float oacc[8][4];
#pragma unroll
    for (int nf = 0; nf < 8; ++nf)
#pragma unroll
        for (int c = 0; c < 4; ++c) oacc[nf][c] = 0.f;

    int vcol = (lane >> 4) * 4;   // d-block select within x4t pair
    uint32_t vq[2][4];
    ldsm_x4t(vq[0], vb + 4u*((0 + a_row)*VST + vcol));  // it=0: kc=0, np=0
#pragma unroll
    for (int it = 0; it < 44; ++it) {
        int cur = it & 1;
        if (it + 1 < 44) {
            int kc1 = (it + 1) >> 2, np1 = (it + 1) & 3;
            ldsm_x4t(vq[cur ^ 1], vb + 4u*((kc1*16 + a_row)*VST + np1*8 + vcol));
        }
        int kc = it >> 2, np = it & 3;
        uint32_t af[4];
        af[0] = p2[4*kc    ];
        af[1] = p2[4*kc + 1];
        af[2] = p2[4*kc + 2];
        af[3] = p2[4*kc + 3];
        uint32_t bf0[2] = { vq[cur][0], vq[cur][1] };
        uint32_t bf1[2] = { vq[cur][2], vq[cur][3] };
        mma16(oacc[np*2    ], af, bf0);
        mma16(oacc[np*2 + 1], af, bf1);
    }

#pragma unroll
    for (int nf = 0; nf < 8; ++nf) {
#pragma unroll
        for (int i = 0; i < 2; ++i) {
            int gr = r0 + g + i*8;
            float sc = i ? i1 : i0;
            int col = h*DD + nf*8 + tg*2;
            uint32_t w = packh2(oacc[nf][i*2 + 0] * sc, oacc[nf][i*2 + 1] * sc);
            *(uint32_t*)&O[((size_t)b*TT + gr)*CC + col] = w;
        }
    }
}

static const int ATTN_SMEM = (112*QST + JP*KST + JP*VST) * (int)sizeof(uint32_t); // 66816
static const int GEMM_SMEM = STG * (int)STAGE_B;   // 61440

extern "C" void kernel_launch(void* const* d_in, const int* in_sizes, int n_in,
                              void* d_out, int out_size)
{
    (void)in_sizes; (void)n_in; (void)out_size;
    const float* x   = (const float*)d_in[0];
    const float* wq  = (const float*)d_in[1];
    const float* qg  = (const float*)d_in[2];
    const float* qb  = (const float*)d_in[3];
    const float* qm  = (const float*)d_in[4];
    const float* qv  = (const float*)d_in[5];
    const float* wk  = (const float*)d_in[6];
    const float* kg  = (const float*)d_in[7];
    const float* kb  = (const float*)d_in[8];
    const float* km  = (const float*)d_in[9];
    const float* kv_ = (const float*)d_in[10];
    const float* wv  = (const float*)d_in[11];
    const float* vg  = (const float*)d_in[12];
    const float* vb  = (const float*)d_in[13];
    const float* vm  = (const float*)d_in[14];
    const float* vv_ = (const float*)d_in[15];
    const float* Wq  = (const float*)d_in[16];
    const float* Wk  = (const float*)d_in[17];
    const float* Wv  = (const float*)d_in[18];
    const float* Wo  = (const float*)d_in[19];
    const float* bo  = (const float*)d_in[20];
    float* out = (float*)d_out;

    __half *qc, *kc, *vc, *Qp, *Kp, *Vp, *Op;
    uint32_t *Wqt, *Wkt, *Wvt, *Wot;
    cudaGetSymbolAddress((void**)&qc, g_qc);
    cudaGetSymbolAddress((void**)&kc, g_kc);
    cudaGetSymbolAddress((void**)&vc, g_vc);
    cudaGetSymbolAddress((void**)&Qp, g_Q);
    cudaGetSymbolAddress((void**)&Kp, g_K);
    cudaGetSymbolAddress((void**)&Vp, g_V);
    cudaGetSymbolAddress((void**)&Op, g_O);
    cudaGetSymbolAddress((void**)&Wqt, g_Wqt);
    cudaGetSymbolAddress((void**)&Wkt, g_Wkt);
    cudaGetSymbolAddress((void**)&Wvt, g_Wvt);
    cudaGetSymbolAddress((void**)&Wot, g_Wot);

    // 0. weight conversion
    dim3 wg(CC/32, CC/32, 4);
    cvt_weights<<<wg, dim3(32,32)>>>(Wq, Wk, Wv, Wo);

    // 1. fused conv projections
    dwbn_fused<<<BB*HH, CC>>>(x, wq, qg, qb, qm, qv,
                              wk, kg, kb, km, kv_,
                              wv, vg, vb, vm, vv_, qc, kc, vc);

    // 2. merged Q/K/V dense projections
    cudaFuncSetAttribute(gemm_qkv, cudaFuncAttributeMaxDynamicSharedMemorySize, GEMM_SMEM);
    cudaFuncSetAttribute(gemm_out, cudaFuncAttributeMaxDynamicSharedMemorySize, GEMM_SMEM);
    gemm_qkv<<<1686, 256, GEMM_SMEM>>>(qc, kc, vc, Wqt, Wkt, Wvt, Qp, Kp, Vp);

    // 3. attention (exact 112-row tiling)
    cudaFuncSetAttribute(attn_f16, cudaFuncAttributeMaxDynamicSharedMemorySize, ATTN_SMEM);
    dim3 ga(7, BB*NHEAD);   // 7 x 384
    attn_f16<<<ga, ATHR, ATTN_SMEM>>>(Qp, Kp, Vp, Op);

    // 4. output projection (+bias, fp32 out)
    gemm_out<<<1176, 256, GEMM_SMEM>>>(Op, Wot, bo, out);
}